// round 12
// baseline (speedup 1.0000x reference)
#include <cuda_runtime.h>
#include <cstdint>

// ConstituencyMFVI: B=8, N=192, 3 iterations.
// R12 = R11 engine (2 independent CTAs/SM, cp.async.bulk tile load,
// half-warp-per-row smem dots + shfl reduce) plus:
//  1) dynamic longest-first work stealing (global atomic counter, reset via
//     cudaMemsetAsync each launch) -> kills ragged tail / cost imbalance.
//  2) CROWS 128->144 (3 chunks x 48 rows, 112.9KB smem, still 2 CTAs/SM)
//     -> overflow gmem rows 10.5 -> 5.9 avg. Rare rows 176+ (i<15) handled
//     in an early short branch to keep common-path register count.

#define NDIM    192
#define CROWS   144
#define CHROWS  48
#define THREADS 512
#define NTILES  (8 * NDIM)          // 1536
#define BUF_FLOATS (CROWS * NDIM)   // 27648

// layout: [32 floats mbar/ctrl][buf][sigA][sigB][partial]
static const int SMEM_BYTES = (32 + BUF_FLOATS + 3 * NDIM) * 4;   // 112960

__device__ unsigned g_tile_ctr;     // reset to 0 by kernel_launch each call

__device__ __forceinline__ unsigned smem_u32(const void* p) {
    return (unsigned)__cvta_generic_to_shared(p);
}
__device__ __forceinline__ float sigmoidf_(float x) {
    return 1.0f / (1.0f + __expf(-x));
}
__device__ __forceinline__ void mbar_wait(unsigned addr, int phase) {
    asm volatile(
        "{\n\t.reg .pred P;\n\t"
        "W_%=:\n\t"
        "mbarrier.try_wait.parity.acquire.cta.shared::cta.b64 P, [%0], %1, 0x989680;\n\t"
        "@P bra.uni D_%=;\n\t"
        "bra.uni W_%=;\n\t"
        "D_%=:\n\t}"
        :: "r"(addr), "r"((unsigned)phase) : "memory");
}
// counter -> tile id, largest tiles (small i) first
__device__ __forceinline__ int map_tile(unsigned c) {
    return (c < NTILES) ? (int)((c & 7u) * NDIM + (c >> 3)) : (1 << 30);
}

// Issue 3 bulk-copy chunks (48 rows) for tile g (tid 0 only).
__device__ __forceinline__ void issue_tile(const float* __restrict__ s_pair,
                                           int g, float* buf, unsigned mbar0)
{
    asm volatile("fence.proxy.async.shared::cta;" ::: "memory");
    const bool valid = (g < NTILES);
    const int  i = valid ? (g % NDIM) : 0;
    const int  nRows = NDIM - 1 - i;
    const float* src0 = s_pair + (size_t)g * (NDIM * NDIM)
                      + (size_t)(i + 1) * NDIM;
    #pragma unroll
    for (int c = 0; c < 3; ++c) {
        int nr = nRows - c * CHROWS;
        if (nr > CHROWS) nr = CHROWS;
        unsigned bytes = (valid && nr > 0) ? (unsigned)(nr * NDIM * 4) : 0u;
        unsigned mb = mbar0 + 8 * c;
        asm volatile("mbarrier.arrive.expect_tx.shared.b64 _, [%0], %1;"
                     :: "r"(mb), "r"(bytes) : "memory");
        if (bytes) {
            unsigned dst = smem_u32(buf + c * (CHROWS * NDIM));
            asm volatile(
                "cp.async.bulk.shared::cta.global.mbarrier::complete_tx::bytes "
                "[%0], [%1], %2, [%3];"
                :: "r"(dst), "l"(src0 + c * (CHROWS * NDIM)), "r"(bytes), "r"(mb)
                : "memory");
        }
    }
}

__global__ void __launch_bounds__(THREADS, 2)
mfvi_kernel(const float* __restrict__ s_span,
            const float* __restrict__ s_pair,
            float* __restrict__ out)
{
    extern __shared__ float smem[];
    uint64_t* mbar  = reinterpret_cast<uint64_t*>(smem);    // [3]
    int*  gslot     = reinterpret_cast<int*>(smem) + 6;     // [2] cur,next
    float* buf      = smem + 32;                            // [144][192]
    float* sigA     = buf + BUF_FLOATS;                     // [192]
    float* sigB     = sigA + NDIM;                          // [192]
    float* partial  = sigB + NDIM;                          // [192]

    const int tid = threadIdx.x;
    const int hw  = tid >> 4;        // half-warp 0..31
    const int ll  = tid & 15;
    const unsigned mb0 = smem_u32(&mbar[0]);

    if (tid == 0) {
        #pragma unroll
        for (int s = 0; s < 3; ++s)
            asm volatile("mbarrier.init.shared.b64 [%0], 1;"
                         :: "r"(smem_u32(&mbar[s])) : "memory");
        asm volatile("fence.proxy.async.shared::cta;" ::: "memory");
        gslot[0] = map_tile(atomicAdd(&g_tile_ctr, 1u));
    }
    __syncthreads();

    int g = gslot[0];
    if (tid == 0) issue_tile(s_pair, g, buf, mb0);

    int n = 0;
    while (g < NTILES) {
        const int ph = n & 1;
        if (tid == 0)
            gslot[1] = map_tile(atomicAdd(&g_tile_ctr, 1u));

        const int i        = g % NDIM;
        const int rowStart = i + 1;
        const int nRows    = NDIM - rowStart;
        const float* gbase = s_pair + (size_t)g * (NDIM * NDIM);

        float span_j = 0.0f, s_prev = 0.5f, vi = 0.0f, vjj = 0.0f;
        if (tid < NDIM) {
            span_j = s_span[(size_t)g * NDIM + tid];
            s_prev = sigmoidf_(span_j);
            sigA[tid] = s_prev;
            sigB[tid] = s_prev;      // k<=i entries stay sig0 in both buffers
        }
        __syncthreads();
        const float s0i = sigA[i];   // sig[i] constant across iterations

        #pragma unroll
        for (int it = 0; it < 3; ++it) {
            const float* sg = (it == 1) ? sigB : sigA;
            const float4* sg4 = reinterpret_cast<const float4*>(sg);
            const float4 s0 = sg4[ll], s1 = sg4[ll + 16], s2 = sg4[ll + 32];

            // Rare overflow rows 176..190 (only when i < 15): short early
            // branch so its registers don't overlap the main accumulators.
            if (176 < nRows) {
                const int r = 176 + hw;      // needs hw < 15
                float dr = 0.0f;
                if (r < nRows) {
                    const float4* rp = reinterpret_cast<const float4*>(
                        gbase + (size_t)(rowStart + r) * NDIM);
                    float4 a = __ldg(rp + ll), b = __ldg(rp + ll + 16),
                           e = __ldg(rp + ll + 32);
                    dr = a.x * s0.x + a.y * s0.y + a.z * s0.z + a.w * s0.w
                       + b.x * s1.x + b.y * s1.y + b.z * s1.z + b.w * s1.w
                       + e.x * s2.x + e.y * s2.y + e.z * s2.z + e.w * s2.w;
                }
                #pragma unroll
                for (int off = 8; off >= 1; off >>= 1)
                    dr += __shfl_xor_sync(0xffffffffu, dr, off);
                if (ll == 8 && r < nRows) partial[r] = dr;
            }

            float d[6] = {0.f, 0.f, 0.f, 0.f, 0.f, 0.f};

            // d[5]: overflow rows 144+hw from gmem/L2 first (latency
            // overlaps the chunk mbar waits in it==0).
            {
                const int r = CROWS + hw;
                if (r < nRows) {
                    const float4* rp = reinterpret_cast<const float4*>(
                        gbase + (size_t)(rowStart + r) * NDIM);
                    float4 a = __ldg(rp + ll), b = __ldg(rp + ll + 16),
                           e = __ldg(rp + ll + 32);
                    d[5] = a.x * s0.x + a.y * s0.y + a.z * s0.z + a.w * s0.w
                         + b.x * s1.x + b.y * s1.y + b.z * s1.z + b.w * s1.w
                         + e.x * s2.x + e.y * s2.y + e.z * s2.z + e.w * s2.w;
                }
            }
            // SMEM rows: d[t<4] = row hw+32t; d[4] = row 128+hw (hw<16).
            // Chunk waits (48-row chunks): c0 before t=0, c1 before t=1,
            // c2 before t=3.
            #pragma unroll
            for (int t = 0; t < 5; ++t) {
                if (it == 0) {
                    if (t == 0) mbar_wait(mb0 + 0,  ph);
                    if (t == 1) mbar_wait(mb0 + 8,  ph);
                    if (t == 3) mbar_wait(mb0 + 16, ph);
                }
                const int r = (t < 4) ? (hw + 32 * t) : (128 + hw);
                const bool ok = (t < 4 || hw < 16) && (r < nRows);
                if (ok) {
                    const float4* rp = reinterpret_cast<const float4*>(
                        buf + (size_t)r * NDIM);
                    float4 a = rp[ll], b = rp[ll + 16], e = rp[ll + 32];
                    d[t] = a.x * s0.x + a.y * s0.y + a.z * s0.z + a.w * s0.w
                         + b.x * s1.x + b.y * s1.y + b.z * s1.z + b.w * s1.w
                         + e.x * s2.x + e.y * s2.y + e.z * s2.z + e.w * s2.w;
                }
            }
            #pragma unroll
            for (int off = 8; off >= 1; off >>= 1)
                #pragma unroll
                for (int t = 0; t < 6; ++t)
                    d[t] += __shfl_xor_sync(0xffffffffu, d[t], off);
            #pragma unroll
            for (int t = 0; t < 6; ++t) {
                const int r = (t < 4) ? (hw + 32 * t)
                            : (t == 4 ? (128 + hw) : (CROWS + hw));
                const bool ok = (t != 4 || hw < 16) && (r < nRows);
                if (ll == t && ok) partial[r] = d[t];
            }
            __syncthreads();

            // All buffer reads for this tile are done after iter-3 dots:
            // start the next tile's TMA (overlaps combiner + next setup).
            if (it == 2 && tid == 0)
                issue_tile(s_pair, gslot[1], buf, mb0);

            if (it == 0 && tid < NDIM && tid > i) {
                const int r = tid - rowStart;
                if (r < CROWS) {
                    vi  = buf[(size_t)r * NDIM + i];
                    vjj = buf[(size_t)r * NDIM + tid];
                } else {
                    vi  = __ldg(gbase + (size_t)tid * NDIM + i);
                    vjj = __ldg(gbase + (size_t)tid * NDIM + tid);
                }
            }
            if (tid < NDIM) {
                if (tid > i) {
                    float q = span_j + partial[tid - rowStart]
                            - s0i * vi - s_prev * vjj;
                    s_prev = sigmoidf_(q);
                    if (it == 0) sigB[tid] = s_prev;
                    else if (it == 1) sigA[tid] = s_prev;
                }
                if (it == 2) out[(size_t)g * NDIM + tid] = s_prev;
            }
            __syncthreads();
        }
        g = gslot[1];
        ++n;
    }
}

extern "C" void kernel_launch(void* const* d_in, const int* in_sizes, int n_in,
                              void* d_out, int out_size)
{
    (void)in_sizes; (void)n_in; (void)out_size;
    const float* s_span = (const float*)d_in[0];
    const float* s_pair = (const float*)d_in[1];
    // d_in[2] = mask: analytic (strict upper triangle), not needed.
    float* out = (float*)d_out;

    // Reset the work-stealing counter (graph-capturable memset node).
    void* ctr_addr = nullptr;
    cudaGetSymbolAddress(&ctr_addr, g_tile_ctr);
    cudaMemsetAsync(ctr_addr, 0, sizeof(unsigned));

    int nsm = 148;
    cudaDeviceGetAttribute(&nsm, cudaDevAttrMultiProcessorCount, 0);
    if (nsm <= 0) nsm = 148;
    int grid = 2 * nsm;                 // 2 persistent CTAs per SM
    if (grid > NTILES) grid = NTILES;

    cudaFuncSetAttribute(mfvi_kernel,
                         cudaFuncAttributeMaxDynamicSharedMemorySize, SMEM_BYTES);

    mfvi_kernel<<<grid, THREADS, SMEM_BYTES>>>(s_span, s_pair, out);
}

// round 13
// speedup vs baseline: 1.0067x; 1.0067x over previous
#include <cuda_runtime.h>
#include <cstdint>

// ConstituencyMFVI: B=8, N=192, 3 iterations.
// R13 = R11 engine VERBATIM (2 independent CTAs/SM, 512 thr, 100.7KB smem,
// cp.async.bulk 4x32-row chunk load, half-warp-per-row smem dots + shfl
// reduce, overflow rows >=128 from gmem/L2) + ONE change: dynamic
// longest-first work stealing (global atomic counter, graph-safe
// cudaMemsetAsync reset; counter c -> tile (c&7)*192 + (c>>3), so big tiles
// first and the ragged tail is filled with tiny tiles).

#define NDIM    192
#define CROWS   128
#define THREADS 512
#define NTILES  (8 * NDIM)          // 1536
#define BUF_FLOATS (CROWS * NDIM)   // 24576

// layout: [mbar 4x8B = 8 floats][gslot 2 ints][pad][buf][sigA][sigB][partial]
static const int SMEM_BYTES = (16 + BUF_FLOATS + 3 * NDIM) * 4;   // 100672

__device__ unsigned g_tile_ctr;     // reset each launch by kernel_launch

__device__ __forceinline__ unsigned smem_u32(const void* p) {
    return (unsigned)__cvta_generic_to_shared(p);
}
__device__ __forceinline__ float sigmoidf_(float x) {
    return 1.0f / (1.0f + __expf(-x));
}
__device__ __forceinline__ void mbar_wait(unsigned addr, int phase) {
    asm volatile(
        "{\n\t.reg .pred P;\n\t"
        "W_%=:\n\t"
        "mbarrier.try_wait.parity.acquire.cta.shared::cta.b64 P, [%0], %1, 0x989680;\n\t"
        "@P bra.uni D_%=;\n\t"
        "bra.uni W_%=;\n\t"
        "D_%=:\n\t}"
        :: "r"(addr), "r"((unsigned)phase) : "memory");
}
// counter -> tile id, largest tiles (small i) first
__device__ __forceinline__ int map_tile(unsigned c) {
    return (c < NTILES) ? (int)((c & 7u) * NDIM + (c >> 3)) : (1 << 30);
}

// Issue 4 bulk-copy chunks (32 rows each) for tile g (tid 0 only).
__device__ __forceinline__ void issue_tile(const float* __restrict__ s_pair,
                                           int g, float* buf, unsigned mbar0)
{
    asm volatile("fence.proxy.async.shared::cta;" ::: "memory");
    const bool valid = (g < NTILES);
    const int  i = valid ? (g % NDIM) : 0;
    const int  nRows = NDIM - 1 - i;
    const float* src0 = s_pair + (size_t)g * (NDIM * NDIM)
                      + (size_t)(i + 1) * NDIM;
    #pragma unroll
    for (int c = 0; c < 4; ++c) {
        int nr = nRows - c * 32;
        if (nr > 32) nr = 32;
        unsigned bytes = (valid && nr > 0) ? (unsigned)(nr * NDIM * 4) : 0u;
        unsigned mb = mbar0 + 8 * c;
        asm volatile("mbarrier.arrive.expect_tx.shared.b64 _, [%0], %1;"
                     :: "r"(mb), "r"(bytes) : "memory");
        if (bytes) {
            unsigned dst = smem_u32(buf + c * (32 * NDIM));
            asm volatile(
                "cp.async.bulk.shared::cta.global.mbarrier::complete_tx::bytes "
                "[%0], [%1], %2, [%3];"
                :: "r"(dst), "l"(src0 + c * (32 * NDIM)), "r"(bytes), "r"(mb)
                : "memory");
        }
    }
}

__global__ void __launch_bounds__(THREADS, 2)
mfvi_kernel(const float* __restrict__ s_span,
            const float* __restrict__ s_pair,
            float* __restrict__ out)
{
    extern __shared__ float smem[];
    uint64_t* mbar = reinterpret_cast<uint64_t*>(smem);   // [4]
    int* gslot     = reinterpret_cast<int*>(smem) + 8;    // [2]: cur, next
    float* buf     = smem + 16;                           // [128][192]
    float* sigA    = buf + BUF_FLOATS;                    // [192]
    float* sigB    = sigA + NDIM;                         // [192]
    float* partial = sigB + NDIM;                         // [192]

    const int tid = threadIdx.x;
    const int hw  = tid >> 4;        // half-warp 0..31
    const int ll  = tid & 15;
    const unsigned mb0 = smem_u32(&mbar[0]);

    if (tid == 0) {
        #pragma unroll
        for (int s = 0; s < 4; ++s)
            asm volatile("mbarrier.init.shared.b64 [%0], 1;"
                         :: "r"(smem_u32(&mbar[s])) : "memory");
        asm volatile("fence.proxy.async.shared::cta;" ::: "memory");
        gslot[0] = map_tile(atomicAdd(&g_tile_ctr, 1u));
    }
    __syncthreads();

    int g = gslot[0];
    if (tid == 0) issue_tile(s_pair, g, buf, mb0);

    int n = 0;
    while (g < NTILES) {
        const int ph = n & 1;
        if (tid == 0)
            gslot[1] = map_tile(atomicAdd(&g_tile_ctr, 1u));

        const int i        = g % NDIM;
        const int rowStart = i + 1;
        const int nRows    = NDIM - rowStart;
        const float* gbase = s_pair + (size_t)g * (NDIM * NDIM);

        float span_j = 0.0f, s_prev = 0.5f, vi = 0.0f, vjj = 0.0f;
        if (tid < NDIM) {
            span_j = s_span[(size_t)g * NDIM + tid];
            s_prev = sigmoidf_(span_j);
            sigA[tid] = s_prev;
            sigB[tid] = s_prev;      // k<=i entries stay sig0 in both buffers
        }
        __syncthreads();
        const float s0i = sigA[i];   // sig[i] constant across iterations

        #pragma unroll
        for (int it = 0; it < 3; ++it) {
            const float* sg = (it == 1) ? sigB : sigA;
            const float4* sg4 = reinterpret_cast<const float4*>(sg);
            const float4 s0 = sg4[ll], s1 = sg4[ll + 16], s2 = sg4[ll + 32];

            float d[6] = {0.f, 0.f, 0.f, 0.f, 0.f, 0.f};

            // Overflow rows (r = 128+hw, 160+hw) from gmem/L2 first:
            // their latency overlaps the chunk mbar waits in it==0.
            #pragma unroll
            for (int ov = 0; ov < 2; ++ov) {
                const int r = CROWS + 32 * ov + hw;
                if (r < nRows) {
                    const float4* rp = reinterpret_cast<const float4*>(
                        gbase + (size_t)(rowStart + r) * NDIM);
                    float4 a = __ldg(rp + ll), b = __ldg(rp + ll + 16),
                           e = __ldg(rp + ll + 32);
                    d[4 + ov] =
                          a.x * s0.x + a.y * s0.y + a.z * s0.z + a.w * s0.w
                        + b.x * s1.x + b.y * s1.y + b.z * s1.z + b.w * s1.w
                        + e.x * s2.x + e.y * s2.y + e.z * s2.z + e.w * s2.w;
                }
            }
            // SMEM chunks: chunk c holds exactly rows 32c..32c+31 (t == c).
            #pragma unroll
            for (int c = 0; c < 4; ++c) {
                if (it == 0) mbar_wait(mb0 + 8 * c, ph);
                const int r = hw + 32 * c;
                if (r < nRows) {
                    const float4* rp = reinterpret_cast<const float4*>(
                        buf + (size_t)r * NDIM);
                    float4 a = rp[ll], b = rp[ll + 16], e = rp[ll + 32];
                    d[c] = a.x * s0.x + a.y * s0.y + a.z * s0.z + a.w * s0.w
                         + b.x * s1.x + b.y * s1.y + b.z * s1.z + b.w * s1.w
                         + e.x * s2.x + e.y * s2.y + e.z * s2.z + e.w * s2.w;
                }
            }
            #pragma unroll
            for (int off = 8; off >= 1; off >>= 1)
                #pragma unroll
                for (int t = 0; t < 6; ++t)
                    d[t] += __shfl_xor_sync(0xffffffffu, d[t], off);
            #pragma unroll
            for (int t = 0; t < 6; ++t) {
                const int r = (t < 4) ? (hw + 32 * t) : (CROWS + 32 * (t - 4) + hw);
                if (ll == t && r < nRows) partial[r] = d[t];
            }
            __syncthreads();

            // All iter-3 buffer reads done -> start next tile's TMA now.
            if (it == 2 && tid == 0)
                issue_tile(s_pair, gslot[1], buf, mb0);

            if (it == 0 && tid < NDIM && tid > i) {
                // mask-correction scalars, read once (data now resident)
                const int r = tid - rowStart;
                if (r < CROWS) {
                    vi  = buf[(size_t)r * NDIM + i];
                    vjj = buf[(size_t)r * NDIM + tid];
                } else {
                    vi  = __ldg(gbase + (size_t)tid * NDIM + i);
                    vjj = __ldg(gbase + (size_t)tid * NDIM + tid);
                }
            }
            if (tid < NDIM) {
                if (tid > i) {
                    float q = span_j + partial[tid - rowStart]
                            - s0i * vi - s_prev * vjj;
                    s_prev = sigmoidf_(q);
                    if (it == 0) sigB[tid] = s_prev;
                    else if (it == 1) sigA[tid] = s_prev;
                }
                if (it == 2) out[(size_t)g * NDIM + tid] = s_prev;
            }
            __syncthreads();
        }
        g = gslot[1];
        ++n;
    }
}

extern "C" void kernel_launch(void* const* d_in, const int* in_sizes, int n_in,
                              void* d_out, int out_size)
{
    (void)in_sizes; (void)n_in; (void)out_size;
    const float* s_span = (const float*)d_in[0];
    const float* s_pair = (const float*)d_in[1];
    // d_in[2] = mask: analytic (strict upper triangle), not needed.
    float* out = (float*)d_out;

    // Reset the work-stealing counter (graph-capturable memset node).
    void* ctr_addr = nullptr;
    cudaGetSymbolAddress(&ctr_addr, g_tile_ctr);
    cudaMemsetAsync(ctr_addr, 0, sizeof(unsigned));

    int nsm = 148;
    cudaDeviceGetAttribute(&nsm, cudaDevAttrMultiProcessorCount, 0);
    if (nsm <= 0) nsm = 148;
    int grid = 2 * nsm;                 // 2 persistent CTAs per SM
    if (grid > NTILES) grid = NTILES;

    cudaFuncSetAttribute(mfvi_kernel,
                         cudaFuncAttributeMaxDynamicSharedMemorySize, SMEM_BYTES);

    mfvi_kernel<<<grid, THREADS, SMEM_BYTES>>>(s_span, s_pair, out);
}